// round 12
// baseline (speedup 1.0000x reference)
#include <cuda_runtime.h>
#include <cuda_fp16.h>
#include <math.h>

#define NN 50000
#define EE 500000
#define HH 128
#define NHH 8
// DH = 16, scale = 0.25 (folded into q GEMM)

#define MAXDEG_SMEM 64

// ---------------- scratch (device globals; no runtime alloc) ----------------
__device__ float g_buf1[(size_t)NN * 256];  // gin hidden (N,128) then FFN hidden (N,256)
__device__ float g_agg [(size_t)NN * HH];   // z = h+agg -> xl (in-place)
__device__ float g_q   [(size_t)NN * HH];
__device__ float g_k   [(size_t)NN * HH];
__device__ float g_v   [(size_t)NN * HH];
__device__ float g_ao  [(size_t)NN * HH];   // xa
__device__ float g_hc  [(size_t)NN * HH];   // hc (materialized by ffn1 staging)
__device__ float g_sum  [3][HH];
__device__ float g_sumsq[3][HH];
__device__ float g_bnA  [3][HH];
__device__ float g_bnB  [3][HH];
// CSR scratch
__device__ int  g_cnt_s[NN];
__device__ int  g_cnt_d[NN];
__device__ int  g_rp_s[NN + 1];
__device__ int  g_rp_d[NN + 1];
__device__ int  g_bsum[2][64];
__device__ int2 g_eps[EE];   // (dst, eid) sorted by src
__device__ int2 g_epd[EE];   // (src, eid) sorted by dst

// ---------------- small helpers ----------------
__device__ __forceinline__ void redf(float* p, float v) {
    asm volatile("red.global.add.f32 [%0], %1;" :: "l"(p), "f"(v) : "memory");
}

// ---------------- CSR build ----------------
__global__ void k_hist(const int* __restrict__ src, const int* __restrict__ dst,
                       int* __restrict__ cs, int* __restrict__ cd) {
    int e = blockIdx.x * 256 + threadIdx.x;
    if (e >= EE) return;
    atomicAdd(&cs[src[e]], 1);
    atomicAdd(&cd[dst[e]], 1);
}

__global__ __launch_bounds__(1024) void k_scan_block(const int* __restrict__ cnt,
                                                     int* __restrict__ excl,
                                                     int* __restrict__ bsum) {
    __shared__ int sm[1024];
    int i = blockIdx.x * 1024 + threadIdx.x;
    int v = (i < NN) ? cnt[i] : 0;
    sm[threadIdx.x] = v;
    __syncthreads();
#pragma unroll
    for (int off = 1; off < 1024; off <<= 1) {
        int t = (threadIdx.x >= off) ? sm[threadIdx.x - off] : 0;
        __syncthreads();
        sm[threadIdx.x] += t;
        __syncthreads();
    }
    if (i <= NN) excl[i] = sm[threadIdx.x] - v;
    if (threadIdx.x == 1023) bsum[blockIdx.x] = sm[1023];
}

__global__ void k_scan_tops(int* __restrict__ bsum, int G) {
    if (threadIdx.x == 0) {
        int acc = 0;
        for (int b = 0; b < G; b++) { int t = bsum[b]; bsum[b] = acc; acc += t; }
    }
}

__global__ __launch_bounds__(1024) void k_scan_add(int* __restrict__ excl,
                                                   const int* __restrict__ bsum) {
    int i = blockIdx.x * 1024 + threadIdx.x;
    if (i <= NN) excl[i] += bsum[blockIdx.x];
}

// consumes the histogram counts via atomicSub (no separate fill arrays)
__global__ void k_scatter(const int* __restrict__ src, const int* __restrict__ dst,
                          const int* __restrict__ rps, const int* __restrict__ rpd,
                          int* __restrict__ cs, int* __restrict__ cd,
                          int2* __restrict__ eps, int2* __restrict__ epd) {
    int e = blockIdx.x * 256 + threadIdx.x;
    if (e >= EE) return;
    int s = src[e], d = dst[e];
    int ps = rps[s] + atomicSub(&cs[s], 1) - 1;
    eps[ps] = make_int2(d, e);
    int pd = rpd[d] + atomicSub(&cd[d], 1) - 1;
    epd[pd] = make_int2(s, e);
}

// ---------------- GINE aggregate over dst-CSR (warp per node, no atomics) -------
__global__ __launch_bounds__(256) void k_agg_csr(
    const float* __restrict__ h, const float* __restrict__ ea,
    const int* __restrict__ rpd, const int2* __restrict__ epd,
    float* __restrict__ z)
{
    int node = blockIdx.x * 8 + (threadIdx.x >> 5);
    if (node >= NN) return;
    int lane = threadIdx.x & 31;
    int j0 = rpd[node], j1 = rpd[node + 1];
    float4 acc = *(const float4*)(h + (size_t)node * HH + lane * 4);
    for (int j = j0; j < j1; j++) {
        int2 pr = __ldg(&epd[j]);
        float4 hv = *(const float4*)(h + (size_t)pr.x * HH + lane * 4);
        float4 ev = __ldcs((const float4*)(ea + (size_t)pr.y * HH + lane * 4));
        acc.x += fmaxf(hv.x + ev.x, 0.f);
        acc.y += fmaxf(hv.y + ev.y, 0.f);
        acc.z += fmaxf(hv.z + ev.z, 0.f);
        acc.w += fmaxf(hv.w + ev.w, 0.f);
    }
    *(float4*)(z + (size_t)node * HH + lane * 4) = acc;
}

// ---------------- fused sparse attention over src-CSR (warp per node) ------------
__global__ __launch_bounds__(256) void k_attn_csr(
    const float* __restrict__ h, const float* __restrict__ q,
    const float* __restrict__ k, const float* __restrict__ v,
    const int* __restrict__ rps, const int2* __restrict__ eps,
    float* __restrict__ xa, float* __restrict__ sum, float* __restrict__ sumsq)
{
    __shared__ float pbuf[8][MAXDEG_SMEM][NHH];
    __shared__ float ss[HH], sq[HH];
    if (threadIdx.x < HH) { ss[threadIdx.x] = 0.f; sq[threadIdx.x] = 0.f; }
    __syncthreads();
    int wid = threadIdx.x >> 5;
    int lane = threadIdx.x & 31;
    int node = blockIdx.x * 8 + wid;
    if (node < NN) {
        int j0 = rps[node], j1 = rps[node + 1];
        int deg = j1 - j0;
        int hd = lane >> 2, t = lane & 3;
        float4 qv = *(const float4*)(q + (size_t)node * HH + lane * 4);
        float den = 0.f;
        for (int j = 0; j < deg; j++) {
            int2 pr = __ldg(&eps[j0 + j]);
            float4 kv = *(const float4*)(k + (size_t)pr.x * HH + lane * 4);
            float part = qv.x * kv.x + qv.y * kv.y + qv.z * kv.z + qv.w * kv.w;
            part += __shfl_xor_sync(0xffffffffu, part, 1);
            part += __shfl_xor_sync(0xffffffffu, part, 2);
            float pe = expf(part);
            den += pe;
            if (j < MAXDEG_SMEM && t == 0) pbuf[wid][j][hd] = pe;
        }
        __syncwarp();
        float inv = (deg > 0) ? 1.f / den : 0.f;
        float4 acc = make_float4(0.f, 0.f, 0.f, 0.f);
        for (int j = 0; j < deg; j++) {
            int2 pr = __ldg(&eps[j0 + j]);
            float w;
            if (j < MAXDEG_SMEM) {
                w = pbuf[wid][j][hd] * inv;
            } else {
                float4 kv = *(const float4*)(k + (size_t)pr.x * HH + lane * 4);
                float part = qv.x * kv.x + qv.y * kv.y + qv.z * kv.z + qv.w * kv.w;
                part += __shfl_xor_sync(0xffffffffu, part, 1);
                part += __shfl_xor_sync(0xffffffffu, part, 2);
                w = expf(part) * inv;
            }
            float4 vv = *(const float4*)(v + (size_t)pr.x * HH + lane * 4);
            acc.x += w * vv.x; acc.y += w * vv.y;
            acc.z += w * vv.z; acc.w += w * vv.w;
        }
        float4 hv = *(const float4*)(h + (size_t)node * HH + lane * 4);
        float4 o = make_float4(hv.x + acc.x, hv.y + acc.y, hv.z + acc.z, hv.w + acc.w);
        *(float4*)(xa + (size_t)node * HH + lane * 4) = o;
        atomicAdd(&ss[lane * 4 + 0], o.x); atomicAdd(&sq[lane * 4 + 0], o.x * o.x);
        atomicAdd(&ss[lane * 4 + 1], o.y); atomicAdd(&sq[lane * 4 + 1], o.y * o.y);
        atomicAdd(&ss[lane * 4 + 2], o.z); atomicAdd(&sq[lane * 4 + 2], o.z * o.z);
        atomicAdd(&ss[lane * 4 + 3], o.w); atomicAdd(&sq[lane * 4 + 3], o.w * o.w);
    }
    __syncthreads();
    if (threadIdx.x < HH) {
        redf(&sum[threadIdx.x], ss[threadIdx.x]);
        redf(&sumsq[threadIdx.x], sq[threadIdx.x]);
    }
}

// ---------------- FP16 tensor-core GEMM (fp32 accumulate) ----------------
// Modes:
//   qkv_mode:     gridDim.y=3 selects (W0,C0,scale0)/(W1,C1)/(W2,C2); n0=0.
//   combine_mode: A := bnA0*A + bnB0 + bnA1*A2 + bnB1 (computed at staging);
//                 blocks with blockIdx.y==0 also write it to hc_out.
//   default:      n0 = blockIdx.y*128.
__global__ __launch_bounds__(256) void k_gemm_tc(
    const float* __restrict__ A, const float* __restrict__ A2,
    const float* __restrict__ W0, const float* __restrict__ W1, const float* __restrict__ W2,
    const float* __restrict__ bias0, const float* __restrict__ bias1, const float* __restrict__ bias2,
    const float* __restrict__ res,
    float* __restrict__ C0, float* __restrict__ C1, float* __restrict__ C2,
    float* __restrict__ hc_out,
    int M, int Nc, int K, float scale0, int do_relu,
    int qkv_mode, int combine_mode,
    float* __restrict__ stat_sum, float* __restrict__ stat_sq)
{
    __shared__ __half2 As[128][20];
    __shared__ __half2 Bs[128][20];

    const float* W = W0;
    const float* bias = bias0;
    float* C = C0;
    float scale = scale0;
    int n0;
    if (qkv_mode) {
        n0 = 0;
        if (blockIdx.y == 1) { W = W1; bias = bias1; C = C1; scale = 1.f; }
        else if (blockIdx.y == 2) { W = W2; bias = bias2; C = C2; scale = 1.f; }
    } else {
        n0 = blockIdx.y * 128;
    }

    const int m0 = blockIdx.x * 128;
    const int tid = threadIdx.x;
    const int wid = tid >> 5;
    const int lane = tid & 31;
    const int g = lane >> 2;
    const int t = lane & 3;
    const int wm = wid >> 1;
    const int wn = wid & 1;

    float acc[2][8][4];
#pragma unroll
    for (int mt = 0; mt < 2; mt++)
#pragma unroll
        for (int nt = 0; nt < 8; nt++)
#pragma unroll
            for (int c = 0; c < 4; c++) acc[mt][nt][c] = 0.f;

    for (int k0 = 0; k0 < K; k0 += 32) {
#pragma unroll
        for (int i = 0; i < 4; i++) {
            int idx = tid + i * 256;          // 0..1023 float4 slots
            int r = idx >> 3;
            int c4 = (idx & 7) * 4;
            int ch = c4 >> 1;
            int gm = m0 + r;
            float4 va = make_float4(0.f, 0.f, 0.f, 0.f);
            if (gm < M) {
                if (combine_mode) {
                    float4 xlv = *(const float4*)(A  + (size_t)gm * K + k0 + c4);
                    float4 xav = *(const float4*)(A2 + (size_t)gm * K + k0 + c4);
                    float4 ca0 = *(const float4*)&g_bnA[0][k0 + c4];
                    float4 cb0 = *(const float4*)&g_bnB[0][k0 + c4];
                    float4 ca1 = *(const float4*)&g_bnA[1][k0 + c4];
                    float4 cb1 = *(const float4*)&g_bnB[1][k0 + c4];
                    va.x = ca0.x * xlv.x + cb0.x + ca1.x * xav.x + cb1.x;
                    va.y = ca0.y * xlv.y + cb0.y + ca1.y * xav.y + cb1.y;
                    va.z = ca0.z * xlv.z + cb0.z + ca1.z * xav.z + cb1.z;
                    va.w = ca0.w * xlv.w + cb0.w + ca1.w * xav.w + cb1.w;
                    if (blockIdx.y == 0)
                        *(float4*)(hc_out + (size_t)gm * K + k0 + c4) = va;
                } else {
                    va = *(const float4*)(A + (size_t)gm * K + k0 + c4);
                }
            }
            As[r][ch + 0] = __floats2half2_rn(va.x, va.y);
            As[r][ch + 1] = __floats2half2_rn(va.z, va.w);
            float4 vb = *(const float4*)(W + (size_t)(n0 + r) * K + k0 + c4);
            Bs[r][ch + 0] = __floats2half2_rn(vb.x, vb.y);
            Bs[r][ch + 1] = __floats2half2_rn(vb.z, vb.w);
        }
        __syncthreads();

#pragma unroll
        for (int ks = 0; ks < 2; ks++) {
            const int kb = ks * 8;
            unsigned a[2][4];
#pragma unroll
            for (int mt = 0; mt < 2; mt++) {
                int r = wm * 32 + mt * 16 + g;
                a[mt][0] = *(const unsigned*)&As[r][kb + t];
                a[mt][1] = *(const unsigned*)&As[r + 8][kb + t];
                a[mt][2] = *(const unsigned*)&As[r][kb + t + 4];
                a[mt][3] = *(const unsigned*)&As[r + 8][kb + t + 4];
            }
            unsigned b[8][2];
#pragma unroll
            for (int nt = 0; nt < 8; nt++) {
                int r = wn * 64 + nt * 8 + g;
                b[nt][0] = *(const unsigned*)&Bs[r][kb + t];
                b[nt][1] = *(const unsigned*)&Bs[r][kb + t + 4];
            }
#pragma unroll
            for (int mt = 0; mt < 2; mt++)
#pragma unroll
                for (int nt = 0; nt < 8; nt++) {
                    asm volatile(
                        "mma.sync.aligned.m16n8k16.row.col.f32.f16.f16.f32 "
                        "{%0,%1,%2,%3}, {%4,%5,%6,%7}, {%8,%9}, {%0,%1,%2,%3};"
                        : "+f"(acc[mt][nt][0]), "+f"(acc[mt][nt][1]),
                          "+f"(acc[mt][nt][2]), "+f"(acc[mt][nt][3])
                        : "r"(a[mt][0]), "r"(a[mt][1]), "r"(a[mt][2]), "r"(a[mt][3]),
                          "r"(b[nt][0]), "r"(b[nt][1]));
                }
        }
        __syncthreads();
    }

#pragma unroll
    for (int nt = 0; nt < 8; nt++) {
        int gn = n0 + wn * 64 + nt * 8 + 2 * t;
        float b0 = bias[gn], b1 = bias[gn + 1];
        float cs0 = 0.f, cs1 = 0.f, cq0 = 0.f, cq1 = 0.f;
#pragma unroll
        for (int mt = 0; mt < 2; mt++) {
            int row = m0 + wm * 32 + mt * 16 + g;
            if (row < M) {
                float v0 = (acc[mt][nt][0] + b0) * scale;
                float v1 = (acc[mt][nt][1] + b1) * scale;
                if (do_relu) { v0 = fmaxf(v0, 0.f); v1 = fmaxf(v1, 0.f); }
                if (res) {
                    float2 rv = *(const float2*)(res + (size_t)row * Nc + gn);
                    v0 += rv.x; v1 += rv.y;
                }
                *(float2*)(C + (size_t)row * Nc + gn) = make_float2(v0, v1);
                cs0 += v0; cq0 += v0 * v0; cs1 += v1; cq1 += v1 * v1;
            }
            int row2 = row + 8;
            if (row2 < M) {
                float v2 = (acc[mt][nt][2] + b0) * scale;
                float v3 = (acc[mt][nt][3] + b1) * scale;
                if (do_relu) { v2 = fmaxf(v2, 0.f); v3 = fmaxf(v3, 0.f); }
                if (res) {
                    float2 rv = *(const float2*)(res + (size_t)row2 * Nc + gn);
                    v2 += rv.x; v3 += rv.y;
                }
                *(float2*)(C + (size_t)row2 * Nc + gn) = make_float2(v2, v3);
                cs0 += v2; cq0 += v2 * v2; cs1 += v3; cq1 += v3 * v3;
            }
        }
        if (stat_sum) {
#pragma unroll
            for (int off = 4; off <= 16; off <<= 1) {
                cs0 += __shfl_xor_sync(0xffffffffu, cs0, off);
                cs1 += __shfl_xor_sync(0xffffffffu, cs1, off);
                cq0 += __shfl_xor_sync(0xffffffffu, cq0, off);
                cq1 += __shfl_xor_sync(0xffffffffu, cq1, off);
            }
            if (g == 0) {
                redf(&stat_sum[gn], cs0); redf(&stat_sum[gn + 1], cs1);
                redf(&stat_sq[gn],  cq0); redf(&stat_sq[gn + 1],  cq1);
            }
        }
    }
}

// ---------------- BN finalize + apply ----------------
__global__ void k_bnfin01(const float* __restrict__ g0, const float* __restrict__ b0,
                          const float* __restrict__ g1, const float* __restrict__ b1) {
    int w = threadIdx.x >> 7;
    int c = threadIdx.x & 127;
    const float* g = w ? g1 : g0;
    const float* b = w ? b1 : b0;
    float mean = g_sum[w][c] * (1.f / NN);
    float var  = g_sumsq[w][c] * (1.f / NN) - mean * mean;
    float a = g[c] * rsqrtf(var + 1e-5f);
    g_bnA[w][c] = a;
    g_bnB[w][c] = b[c] - mean * a;
}

__global__ void k_bnfin(int which, const float* __restrict__ g, const float* __restrict__ b) {
    int c = threadIdx.x;
    float mean = g_sum[which][c] * (1.f / NN);
    float var  = g_sumsq[which][c] * (1.f / NN) - mean * mean;
    float a = g[c] * rsqrtf(var + 1e-5f);
    g_bnA[which][c] = a;
    g_bnB[which][c] = b[c] - mean * a;
}

__global__ void k_apply(const float* __restrict__ hc, float* __restrict__ out) {
    size_t i = (size_t)blockIdx.x * blockDim.x + threadIdx.x;
    if (i >= (size_t)NN * 32) return;
    int c4 = (int)(i & 31);
    float4 xv = ((const float4*)hc)[i];
    float4 a2 = *(const float4*)&g_bnA[2][c4 * 4];
    float4 b2 = *(const float4*)&g_bnB[2][c4 * 4];
    float4 o;
    o.x = a2.x * xv.x + b2.x;
    o.y = a2.y * xv.y + b2.y;
    o.z = a2.z * xv.z + b2.z;
    o.w = a2.w * xv.w + b2.w;
    ((float4*)out)[i] = o;
}

// ---------------- launcher ----------------
extern "C" void kernel_launch(void* const* d_in, const int* in_sizes, int n_in,
                              void* d_out, int out_size) {
    const float* h      = (const float*)d_in[0];
    const float* eattr  = (const float*)d_in[1];
    const int*   src    = (const int*)d_in[2];
    const int*   dst    = (const int*)d_in[3];
    const float* gin_w1 = (const float*)d_in[4];
    const float* gin_b1 = (const float*)d_in[5];
    const float* gin_w2 = (const float*)d_in[6];
    const float* gin_b2 = (const float*)d_in[7];
    const float* wq = (const float*)d_in[8];
    const float* bq = (const float*)d_in[9];
    const float* wk = (const float*)d_in[10];
    const float* bk = (const float*)d_in[11];
    const float* wv = (const float*)d_in[12];
    const float* bv = (const float*)d_in[13];
    const float* nl_g = (const float*)d_in[14];
    const float* nl_b = (const float*)d_in[15];
    const float* na_g = (const float*)d_in[16];
    const float* na_b = (const float*)d_in[17];
    const float* no_g = (const float*)d_in[18];
    const float* no_b = (const float*)d_in[19];
    const float* ffn1_w = (const float*)d_in[20];
    const float* ffn1_b = (const float*)d_in[21];
    const float* ffn2_w = (const float*)d_in[22];
    const float* ffn2_b = (const float*)d_in[23];

    float* out_hc = (float*)d_out;
    float* out_ea = (float*)d_out + (size_t)NN * HH;

    float *p_buf1, *p_agg, *p_q, *p_k, *p_v, *p_ao, *p_hc, *p_sum, *p_sumsq;
    int *p_cnt_s, *p_cnt_d, *p_rp_s, *p_rp_d, *p_bsum;
    int2 *p_eps, *p_epd;
    cudaGetSymbolAddress((void**)&p_buf1, g_buf1);
    cudaGetSymbolAddress((void**)&p_agg,  g_agg);
    cudaGetSymbolAddress((void**)&p_q,    g_q);
    cudaGetSymbolAddress((void**)&p_k,    g_k);
    cudaGetSymbolAddress((void**)&p_v,    g_v);
    cudaGetSymbolAddress((void**)&p_ao,   g_ao);
    cudaGetSymbolAddress((void**)&p_hc,   g_hc);
    cudaGetSymbolAddress((void**)&p_sum,  g_sum);
    cudaGetSymbolAddress((void**)&p_sumsq, g_sumsq);
    cudaGetSymbolAddress((void**)&p_cnt_s, g_cnt_s);
    cudaGetSymbolAddress((void**)&p_cnt_d, g_cnt_d);
    cudaGetSymbolAddress((void**)&p_rp_s, g_rp_s);
    cudaGetSymbolAddress((void**)&p_rp_d, g_rp_d);
    cudaGetSymbolAddress((void**)&p_bsum, g_bsum);
    cudaGetSymbolAddress((void**)&p_eps, g_eps);
    cudaGetSymbolAddress((void**)&p_epd, g_epd);

    static cudaStream_t s2 = nullptr, s3 = nullptr;
    static cudaEvent_t ev_fork = nullptr, ev_csr = nullptr, ev_join = nullptr, ev_copy = nullptr;
    if (s2 == nullptr) {
        cudaStreamCreateWithFlags(&s2, cudaStreamNonBlocking);
        cudaStreamCreateWithFlags(&s3, cudaStreamNonBlocking);
        cudaEventCreateWithFlags(&ev_fork, cudaEventDisableTiming);
        cudaEventCreateWithFlags(&ev_csr,  cudaEventDisableTiming);
        cudaEventCreateWithFlags(&ev_join, cudaEventDisableTiming);
        cudaEventCreateWithFlags(&ev_copy, cudaEventDisableTiming);
    }

    const int EB = (EE + 255) / 256;        // edge-parallel blocks
    const int NB = (NN + 7) / 8;            // warp-per-node blocks
    const int MB = (NN + 127) / 128;        // gemm row tiles
    const int SG = (NN + 1024) / 1024;      // scan blocks (covers NN+1)

    cudaMemsetAsync(p_cnt_s, 0, NN * sizeof(int));
    cudaMemsetAsync(p_cnt_d, 0, NN * sizeof(int));
    cudaMemsetAsync(p_sum, 0, 3 * HH * sizeof(float));
    cudaMemsetAsync(p_sumsq, 0, 3 * HH * sizeof(float));

    // fork s2 (QKV) and s3 (eattr passthrough copy)
    cudaEventRecord(ev_fork, 0);
    cudaStreamWaitEvent(s2, ev_fork, 0);
    cudaStreamWaitEvent(s3, ev_fork, 0);

    // s3: passthrough copy (ideally copy-engine backed)
    cudaMemcpyAsync(out_ea, eattr, (size_t)EE * HH * sizeof(float),
                    cudaMemcpyDeviceToDevice, s3);
    cudaEventRecord(ev_copy, s3);

    // s2: fused QKV GEMM (one launch, blockIdx.y selects q/k/v)
    k_gemm_tc<<<dim3(MB, 3), 256, 0, s2>>>(
        h, nullptr, wq, wk, wv, bq, bk, bv, nullptr,
        p_q, p_k, p_v, nullptr,
        NN, HH, HH, 0.25f, 0, /*qkv*/1, /*combine*/0, nullptr, nullptr);

    // main: CSR build (both directions)
    k_hist<<<EB, 256>>>(src, dst, p_cnt_s, p_cnt_d);
    k_scan_block<<<SG, 1024>>>(p_cnt_s, p_rp_s, &p_bsum[0]);
    k_scan_block<<<SG, 1024>>>(p_cnt_d, p_rp_d, &p_bsum[64]);
    k_scan_tops<<<1, 32>>>(&p_bsum[0], SG);
    k_scan_tops<<<1, 32>>>(&p_bsum[64], SG);
    k_scan_add<<<SG, 1024>>>(p_rp_s, &p_bsum[0]);
    k_scan_add<<<SG, 1024>>>(p_rp_d, &p_bsum[64]);
    k_scatter<<<EB, 256>>>(src, dst, p_rp_s, p_rp_d, p_cnt_s, p_cnt_d, p_eps, p_epd);
    cudaEventRecord(ev_csr, 0);

    // s2: fused attention (after QKV + CSR)
    cudaStreamWaitEvent(s2, ev_csr, 0);
    k_attn_csr<<<NB, 256, 0, s2>>>(h, p_q, p_k, p_v, p_rp_s, p_eps,
                                   p_ao, &p_sum[1 * HH], &p_sumsq[1 * HH]);
    cudaEventRecord(ev_join, s2);

    // main: GINE aggregate + GIN MLP (stats set 0 fused in second GEMM)
    k_agg_csr<<<NB, 256>>>(h, eattr, p_rp_d, p_epd, p_agg);
    k_gemm_tc<<<dim3(MB, 1), 256>>>(
        p_agg, nullptr, gin_w1, nullptr, nullptr, gin_b1, nullptr, nullptr, nullptr,
        p_buf1, nullptr, nullptr, nullptr,
        NN, HH, HH, 1.f, 1, 0, 0, nullptr, nullptr);
    k_gemm_tc<<<dim3(MB, 1), 256>>>(
        p_buf1, nullptr, gin_w2, nullptr, nullptr, gin_b2, nullptr, nullptr, h,
        p_agg, nullptr, nullptr, nullptr,
        NN, HH, HH, 1.f, 0, 0, 0, &p_sum[0 * HH], &p_sumsq[0 * HH]);

    // join attention branch
    cudaStreamWaitEvent(0, ev_join, 0);

    // finalize BNs 0/1; FFN1 fuses the combine (and materializes hc)
    k_bnfin01<<<1, 256>>>(nl_g, nl_b, na_g, na_b);
    k_gemm_tc<<<dim3(MB, 2), 256>>>(
        p_agg, p_ao, ffn1_w, nullptr, nullptr, ffn1_b, nullptr, nullptr, nullptr,
        p_buf1, nullptr, nullptr, p_hc,
        NN, 256, HH, 1.f, 1, 0, /*combine*/1, nullptr, nullptr);
    k_gemm_tc<<<dim3(MB, 1), 256>>>(
        p_buf1, nullptr, ffn2_w, nullptr, nullptr, ffn2_b, nullptr, nullptr, p_hc,
        p_hc, nullptr, nullptr, nullptr,
        NN, HH, 256, 1.f, 0, 0, 0, &p_sum[2 * HH], &p_sumsq[2 * HH]);
    k_bnfin<<<1, 128>>>(2, no_g, no_b);
    k_apply<<<(NN * 32 + 255) / 256, 256>>>(p_hc, out_hc);

    // join the passthrough copy
    cudaStreamWaitEvent(0, ev_copy, 0);
}

// round 13
// speedup vs baseline: 1.0272x; 1.0272x over previous
#include <cuda_runtime.h>
#include <cuda_fp16.h>
#include <math.h>

#define NN 50000
#define EE 500000
#define HH 128
#define NHH 8
// DH = 16, scale = 0.25 (folded into q GEMM)

#define MAXDEG_SMEM 64

// ---------------- scratch (device globals; no runtime alloc) ----------------
__device__ float g_buf1[(size_t)NN * 256];  // gin hidden (N,128) then FFN hidden (N,256)
__device__ float g_agg [(size_t)NN * HH];   // z = h+agg -> xl (in-place)
__device__ float g_q   [(size_t)NN * HH];
__device__ float g_k   [(size_t)NN * HH];
__device__ float g_v   [(size_t)NN * HH];
__device__ float g_ao  [(size_t)NN * HH];   // xa
__device__ float g_hc  [(size_t)NN * HH];   // hc (materialized by ffn1 staging)
__device__ float g_sum  [3][HH];
__device__ float g_sumsq[3][HH];
__device__ float g_bnA  [3][HH];
__device__ float g_bnB  [3][HH];
// CSR scratch
__device__ int  g_cnt_s[NN];
__device__ int  g_cnt_d[NN];
__device__ int  g_rp_s[NN + 1];
__device__ int  g_rp_d[NN + 1];
__device__ int  g_bsum[2][64];
__device__ int2 g_eps[EE];   // (dst, eid) sorted by src
__device__ int2 g_epd[EE];   // (src, eid) sorted by dst

// ---------------- small helpers ----------------
__device__ __forceinline__ void redf(float* p, float v) {
    asm volatile("red.global.add.f32 [%0], %1;" :: "l"(p), "f"(v) : "memory");
}

// ---------------- CSR build ----------------
__global__ void k_hist(const int* __restrict__ src, const int* __restrict__ dst,
                       int* __restrict__ cs, int* __restrict__ cd) {
    int e = blockIdx.x * 256 + threadIdx.x;
    if (e >= EE) return;
    atomicAdd(&cs[src[e]], 1);
    atomicAdd(&cd[dst[e]], 1);
}

__global__ __launch_bounds__(1024) void k_scan_block(const int* __restrict__ cnt,
                                                     int* __restrict__ excl,
                                                     int* __restrict__ bsum) {
    __shared__ int sm[1024];
    int i = blockIdx.x * 1024 + threadIdx.x;
    int v = (i < NN) ? cnt[i] : 0;
    sm[threadIdx.x] = v;
    __syncthreads();
#pragma unroll
    for (int off = 1; off < 1024; off <<= 1) {
        int t = (threadIdx.x >= off) ? sm[threadIdx.x - off] : 0;
        __syncthreads();
        sm[threadIdx.x] += t;
        __syncthreads();
    }
    if (i <= NN) excl[i] = sm[threadIdx.x] - v;
    if (threadIdx.x == 1023) bsum[blockIdx.x] = sm[1023];
}

__global__ void k_scan_tops(int* __restrict__ bsum, int G) {
    if (threadIdx.x == 0) {
        int acc = 0;
        for (int b = 0; b < G; b++) { int t = bsum[b]; bsum[b] = acc; acc += t; }
    }
}

__global__ __launch_bounds__(1024) void k_scan_add(int* __restrict__ excl,
                                                   const int* __restrict__ bsum) {
    int i = blockIdx.x * 1024 + threadIdx.x;
    if (i <= NN) excl[i] += bsum[blockIdx.x];
}

// consumes the histogram counts via atomicSub (no separate fill arrays)
__global__ void k_scatter(const int* __restrict__ src, const int* __restrict__ dst,
                          const int* __restrict__ rps, const int* __restrict__ rpd,
                          int* __restrict__ cs, int* __restrict__ cd,
                          int2* __restrict__ eps, int2* __restrict__ epd) {
    int e = blockIdx.x * 256 + threadIdx.x;
    if (e >= EE) return;
    int s = src[e], d = dst[e];
    int ps = rps[s] + atomicSub(&cs[s], 1) - 1;
    eps[ps] = make_int2(d, e);
    int pd = rpd[d] + atomicSub(&cd[d], 1) - 1;
    epd[pd] = make_int2(s, e);
}

// ---------------- GINE aggregate over dst-CSR (warp per node, no atomics) -------
// fused eattr passthrough: value already in registers, single streaming store.
__global__ __launch_bounds__(256) void k_agg_csr(
    const float* __restrict__ h, const float* __restrict__ ea,
    const int* __restrict__ rpd, const int2* __restrict__ epd,
    float* __restrict__ z, float* __restrict__ ea_out)
{
    int node = blockIdx.x * 8 + (threadIdx.x >> 5);
    if (node >= NN) return;
    int lane = threadIdx.x & 31;
    int j0 = rpd[node], j1 = rpd[node + 1];
    float4 acc = *(const float4*)(h + (size_t)node * HH + lane * 4);
    for (int j = j0; j < j1; j++) {
        int2 pr = __ldg(&epd[j]);
        float4 hv = *(const float4*)(h + (size_t)pr.x * HH + lane * 4);
        float4 ev = __ldcs((const float4*)(ea + (size_t)pr.y * HH + lane * 4));
        __stcs((float4*)(ea_out + (size_t)pr.y * HH + lane * 4), ev);
        acc.x += fmaxf(hv.x + ev.x, 0.f);
        acc.y += fmaxf(hv.y + ev.y, 0.f);
        acc.z += fmaxf(hv.z + ev.z, 0.f);
        acc.w += fmaxf(hv.w + ev.w, 0.f);
    }
    *(float4*)(z + (size_t)node * HH + lane * 4) = acc;
}

// ---------------- fused sparse attention over src-CSR (warp per node) ------------
__global__ __launch_bounds__(256) void k_attn_csr(
    const float* __restrict__ h, const float* __restrict__ q,
    const float* __restrict__ k, const float* __restrict__ v,
    const int* __restrict__ rps, const int2* __restrict__ eps,
    float* __restrict__ xa, float* __restrict__ sum, float* __restrict__ sumsq)
{
    __shared__ float pbuf[8][MAXDEG_SMEM][NHH];
    __shared__ float ss[HH], sq[HH];
    if (threadIdx.x < HH) { ss[threadIdx.x] = 0.f; sq[threadIdx.x] = 0.f; }
    __syncthreads();
    int wid = threadIdx.x >> 5;
    int lane = threadIdx.x & 31;
    int node = blockIdx.x * 8 + wid;
    if (node < NN) {
        int j0 = rps[node], j1 = rps[node + 1];
        int deg = j1 - j0;
        int hd = lane >> 2, t = lane & 3;
        float4 qv = *(const float4*)(q + (size_t)node * HH + lane * 4);
        float den = 0.f;
        for (int j = 0; j < deg; j++) {
            int2 pr = __ldg(&eps[j0 + j]);
            float4 kv = *(const float4*)(k + (size_t)pr.x * HH + lane * 4);
            float part = qv.x * kv.x + qv.y * kv.y + qv.z * kv.z + qv.w * kv.w;
            part += __shfl_xor_sync(0xffffffffu, part, 1);
            part += __shfl_xor_sync(0xffffffffu, part, 2);
            float pe = expf(part);
            den += pe;
            if (j < MAXDEG_SMEM && t == 0) pbuf[wid][j][hd] = pe;
        }
        __syncwarp();
        float inv = (deg > 0) ? 1.f / den : 0.f;
        float4 acc = make_float4(0.f, 0.f, 0.f, 0.f);
        for (int j = 0; j < deg; j++) {
            int2 pr = __ldg(&eps[j0 + j]);
            float w;
            if (j < MAXDEG_SMEM) {
                w = pbuf[wid][j][hd] * inv;
            } else {
                float4 kv = *(const float4*)(k + (size_t)pr.x * HH + lane * 4);
                float part = qv.x * kv.x + qv.y * kv.y + qv.z * kv.z + qv.w * kv.w;
                part += __shfl_xor_sync(0xffffffffu, part, 1);
                part += __shfl_xor_sync(0xffffffffu, part, 2);
                w = expf(part) * inv;
            }
            float4 vv = *(const float4*)(v + (size_t)pr.x * HH + lane * 4);
            acc.x += w * vv.x; acc.y += w * vv.y;
            acc.z += w * vv.z; acc.w += w * vv.w;
        }
        float4 hv = *(const float4*)(h + (size_t)node * HH + lane * 4);
        float4 o = make_float4(hv.x + acc.x, hv.y + acc.y, hv.z + acc.z, hv.w + acc.w);
        *(float4*)(xa + (size_t)node * HH + lane * 4) = o;
        atomicAdd(&ss[lane * 4 + 0], o.x); atomicAdd(&sq[lane * 4 + 0], o.x * o.x);
        atomicAdd(&ss[lane * 4 + 1], o.y); atomicAdd(&sq[lane * 4 + 1], o.y * o.y);
        atomicAdd(&ss[lane * 4 + 2], o.z); atomicAdd(&sq[lane * 4 + 2], o.z * o.z);
        atomicAdd(&ss[lane * 4 + 3], o.w); atomicAdd(&sq[lane * 4 + 3], o.w * o.w);
    }
    __syncthreads();
    if (threadIdx.x < HH) {
        redf(&sum[threadIdx.x], ss[threadIdx.x]);
        redf(&sumsq[threadIdx.x], sq[threadIdx.x]);
    }
}

// ---------------- FP16 tensor-core GEMM (fp32 accumulate) ----------------
// Modes:
//   qkv_mode:     gridDim.y=3 selects (W0,C0,scale0)/(W1,C1)/(W2,C2); n0=0.
//   combine_mode: A := bnA0*A + bnB0 + bnA1*A2 + bnB1 (computed at staging);
//                 blocks with blockIdx.y==0 also write it to hc_out.
//   default:      n0 = blockIdx.y*128.
__global__ __launch_bounds__(256) void k_gemm_tc(
    const float* __restrict__ A, const float* __restrict__ A2,
    const float* __restrict__ W0, const float* __restrict__ W1, const float* __restrict__ W2,
    const float* __restrict__ bias0, const float* __restrict__ bias1, const float* __restrict__ bias2,
    const float* __restrict__ res,
    float* __restrict__ C0, float* __restrict__ C1, float* __restrict__ C2,
    float* __restrict__ hc_out,
    int M, int Nc, int K, float scale0, int do_relu,
    int qkv_mode, int combine_mode,
    float* __restrict__ stat_sum, float* __restrict__ stat_sq)
{
    __shared__ __half2 As[128][20];
    __shared__ __half2 Bs[128][20];

    const float* W = W0;
    const float* bias = bias0;
    float* C = C0;
    float scale = scale0;
    int n0;
    if (qkv_mode) {
        n0 = 0;
        if (blockIdx.y == 1) { W = W1; bias = bias1; C = C1; scale = 1.f; }
        else if (blockIdx.y == 2) { W = W2; bias = bias2; C = C2; scale = 1.f; }
    } else {
        n0 = blockIdx.y * 128;
    }

    const int m0 = blockIdx.x * 128;
    const int tid = threadIdx.x;
    const int wid = tid >> 5;
    const int lane = tid & 31;
    const int g = lane >> 2;
    const int t = lane & 3;
    const int wm = wid >> 1;
    const int wn = wid & 1;

    float acc[2][8][4];
#pragma unroll
    for (int mt = 0; mt < 2; mt++)
#pragma unroll
        for (int nt = 0; nt < 8; nt++)
#pragma unroll
            for (int c = 0; c < 4; c++) acc[mt][nt][c] = 0.f;

    for (int k0 = 0; k0 < K; k0 += 32) {
#pragma unroll
        for (int i = 0; i < 4; i++) {
            int idx = tid + i * 256;          // 0..1023 float4 slots
            int r = idx >> 3;
            int c4 = (idx & 7) * 4;
            int ch = c4 >> 1;
            int gm = m0 + r;
            float4 va = make_float4(0.f, 0.f, 0.f, 0.f);
            if (gm < M) {
                if (combine_mode) {
                    float4 xlv = *(const float4*)(A  + (size_t)gm * K + k0 + c4);
                    float4 xav = *(const float4*)(A2 + (size_t)gm * K + k0 + c4);
                    float4 ca0 = *(const float4*)&g_bnA[0][k0 + c4];
                    float4 cb0 = *(const float4*)&g_bnB[0][k0 + c4];
                    float4 ca1 = *(const float4*)&g_bnA[1][k0 + c4];
                    float4 cb1 = *(const float4*)&g_bnB[1][k0 + c4];
                    va.x = ca0.x * xlv.x + cb0.x + ca1.x * xav.x + cb1.x;
                    va.y = ca0.y * xlv.y + cb0.y + ca1.y * xav.y + cb1.y;
                    va.z = ca0.z * xlv.z + cb0.z + ca1.z * xav.z + cb1.z;
                    va.w = ca0.w * xlv.w + cb0.w + ca1.w * xav.w + cb1.w;
                    if (blockIdx.y == 0)
                        *(float4*)(hc_out + (size_t)gm * K + k0 + c4) = va;
                } else {
                    va = *(const float4*)(A + (size_t)gm * K + k0 + c4);
                }
            }
            As[r][ch + 0] = __floats2half2_rn(va.x, va.y);
            As[r][ch + 1] = __floats2half2_rn(va.z, va.w);
            float4 vb = *(const float4*)(W + (size_t)(n0 + r) * K + k0 + c4);
            Bs[r][ch + 0] = __floats2half2_rn(vb.x, vb.y);
            Bs[r][ch + 1] = __floats2half2_rn(vb.z, vb.w);
        }
        __syncthreads();

#pragma unroll
        for (int ks = 0; ks < 2; ks++) {
            const int kb = ks * 8;
            unsigned a[2][4];
#pragma unroll
            for (int mt = 0; mt < 2; mt++) {
                int r = wm * 32 + mt * 16 + g;
                a[mt][0] = *(const unsigned*)&As[r][kb + t];
                a[mt][1] = *(const unsigned*)&As[r + 8][kb + t];
                a[mt][2] = *(const unsigned*)&As[r][kb + t + 4];
                a[mt][3] = *(const unsigned*)&As[r + 8][kb + t + 4];
            }
            unsigned b[8][2];
#pragma unroll
            for (int nt = 0; nt < 8; nt++) {
                int r = wn * 64 + nt * 8 + g;
                b[nt][0] = *(const unsigned*)&Bs[r][kb + t];
                b[nt][1] = *(const unsigned*)&Bs[r][kb + t + 4];
            }
#pragma unroll
            for (int mt = 0; mt < 2; mt++)
#pragma unroll
                for (int nt = 0; nt < 8; nt++) {
                    asm volatile(
                        "mma.sync.aligned.m16n8k16.row.col.f32.f16.f16.f32 "
                        "{%0,%1,%2,%3}, {%4,%5,%6,%7}, {%8,%9}, {%0,%1,%2,%3};"
                        : "+f"(acc[mt][nt][0]), "+f"(acc[mt][nt][1]),
                          "+f"(acc[mt][nt][2]), "+f"(acc[mt][nt][3])
                        : "r"(a[mt][0]), "r"(a[mt][1]), "r"(a[mt][2]), "r"(a[mt][3]),
                          "r"(b[nt][0]), "r"(b[nt][1]));
                }
        }
        __syncthreads();
    }

#pragma unroll
    for (int nt = 0; nt < 8; nt++) {
        int gn = n0 + wn * 64 + nt * 8 + 2 * t;
        float b0 = bias[gn], b1 = bias[gn + 1];
        float cs0 = 0.f, cs1 = 0.f, cq0 = 0.f, cq1 = 0.f;
#pragma unroll
        for (int mt = 0; mt < 2; mt++) {
            int row = m0 + wm * 32 + mt * 16 + g;
            if (row < M) {
                float v0 = (acc[mt][nt][0] + b0) * scale;
                float v1 = (acc[mt][nt][1] + b1) * scale;
                if (do_relu) { v0 = fmaxf(v0, 0.f); v1 = fmaxf(v1, 0.f); }
                if (res) {
                    float2 rv = *(const float2*)(res + (size_t)row * Nc + gn);
                    v0 += rv.x; v1 += rv.y;
                }
                *(float2*)(C + (size_t)row * Nc + gn) = make_float2(v0, v1);
                cs0 += v0; cq0 += v0 * v0; cs1 += v1; cq1 += v1 * v1;
            }
            int row2 = row + 8;
            if (row2 < M) {
                float v2 = (acc[mt][nt][2] + b0) * scale;
                float v3 = (acc[mt][nt][3] + b1) * scale;
                if (do_relu) { v2 = fmaxf(v2, 0.f); v3 = fmaxf(v3, 0.f); }
                if (res) {
                    float2 rv = *(const float2*)(res + (size_t)row2 * Nc + gn);
                    v2 += rv.x; v3 += rv.y;
                }
                *(float2*)(C + (size_t)row2 * Nc + gn) = make_float2(v2, v3);
                cs0 += v2; cq0 += v2 * v2; cs1 += v3; cq1 += v3 * v3;
            }
        }
        if (stat_sum) {
#pragma unroll
            for (int off = 4; off <= 16; off <<= 1) {
                cs0 += __shfl_xor_sync(0xffffffffu, cs0, off);
                cs1 += __shfl_xor_sync(0xffffffffu, cs1, off);
                cq0 += __shfl_xor_sync(0xffffffffu, cq0, off);
                cq1 += __shfl_xor_sync(0xffffffffu, cq1, off);
            }
            if (g == 0) {
                redf(&stat_sum[gn], cs0); redf(&stat_sum[gn + 1], cs1);
                redf(&stat_sq[gn],  cq0); redf(&stat_sq[gn + 1],  cq1);
            }
        }
    }
}

// ---------------- BN finalize + apply ----------------
__global__ void k_bnfin01(const float* __restrict__ g0, const float* __restrict__ b0,
                          const float* __restrict__ g1, const float* __restrict__ b1) {
    int w = threadIdx.x >> 7;
    int c = threadIdx.x & 127;
    const float* g = w ? g1 : g0;
    const float* b = w ? b1 : b0;
    float mean = g_sum[w][c] * (1.f / NN);
    float var  = g_sumsq[w][c] * (1.f / NN) - mean * mean;
    float a = g[c] * rsqrtf(var + 1e-5f);
    g_bnA[w][c] = a;
    g_bnB[w][c] = b[c] - mean * a;
}

__global__ void k_bnfin(int which, const float* __restrict__ g, const float* __restrict__ b) {
    int c = threadIdx.x;
    float mean = g_sum[which][c] * (1.f / NN);
    float var  = g_sumsq[which][c] * (1.f / NN) - mean * mean;
    float a = g[c] * rsqrtf(var + 1e-5f);
    g_bnA[which][c] = a;
    g_bnB[which][c] = b[c] - mean * a;
}

__global__ void k_apply(const float* __restrict__ hc, float* __restrict__ out) {
    size_t i = (size_t)blockIdx.x * blockDim.x + threadIdx.x;
    if (i >= (size_t)NN * 32) return;
    int c4 = (int)(i & 31);
    float4 xv = ((const float4*)hc)[i];
    float4 a2 = *(const float4*)&g_bnA[2][c4 * 4];
    float4 b2 = *(const float4*)&g_bnB[2][c4 * 4];
    float4 o;
    o.x = a2.x * xv.x + b2.x;
    o.y = a2.y * xv.y + b2.y;
    o.z = a2.z * xv.z + b2.z;
    o.w = a2.w * xv.w + b2.w;
    ((float4*)out)[i] = o;
}

// ---------------- launcher ----------------
extern "C" void kernel_launch(void* const* d_in, const int* in_sizes, int n_in,
                              void* d_out, int out_size) {
    const float* h      = (const float*)d_in[0];
    const float* eattr  = (const float*)d_in[1];
    const int*   src    = (const int*)d_in[2];
    const int*   dst    = (const int*)d_in[3];
    const float* gin_w1 = (const float*)d_in[4];
    const float* gin_b1 = (const float*)d_in[5];
    const float* gin_w2 = (const float*)d_in[6];
    const float* gin_b2 = (const float*)d_in[7];
    const float* wq = (const float*)d_in[8];
    const float* bq = (const float*)d_in[9];
    const float* wk = (const float*)d_in[10];
    const float* bk = (const float*)d_in[11];
    const float* wv = (const float*)d_in[12];
    const float* bv = (const float*)d_in[13];
    const float* nl_g = (const float*)d_in[14];
    const float* nl_b = (const float*)d_in[15];
    const float* na_g = (const float*)d_in[16];
    const float* na_b = (const float*)d_in[17];
    const float* no_g = (const float*)d_in[18];
    const float* no_b = (const float*)d_in[19];
    const float* ffn1_w = (const float*)d_in[20];
    const float* ffn1_b = (const float*)d_in[21];
    const float* ffn2_w = (const float*)d_in[22];
    const float* ffn2_b = (const float*)d_in[23];

    float* out_hc = (float*)d_out;
    float* out_ea = (float*)d_out + (size_t)NN * HH;

    float *p_buf1, *p_agg, *p_q, *p_k, *p_v, *p_ao, *p_hc, *p_sum, *p_sumsq;
    int *p_cnt_s, *p_cnt_d, *p_rp_s, *p_rp_d, *p_bsum;
    int2 *p_eps, *p_epd;
    cudaGetSymbolAddress((void**)&p_buf1, g_buf1);
    cudaGetSymbolAddress((void**)&p_agg,  g_agg);
    cudaGetSymbolAddress((void**)&p_q,    g_q);
    cudaGetSymbolAddress((void**)&p_k,    g_k);
    cudaGetSymbolAddress((void**)&p_v,    g_v);
    cudaGetSymbolAddress((void**)&p_ao,   g_ao);
    cudaGetSymbolAddress((void**)&p_hc,   g_hc);
    cudaGetSymbolAddress((void**)&p_sum,  g_sum);
    cudaGetSymbolAddress((void**)&p_sumsq, g_sumsq);
    cudaGetSymbolAddress((void**)&p_cnt_s, g_cnt_s);
    cudaGetSymbolAddress((void**)&p_cnt_d, g_cnt_d);
    cudaGetSymbolAddress((void**)&p_rp_s, g_rp_s);
    cudaGetSymbolAddress((void**)&p_rp_d, g_rp_d);
    cudaGetSymbolAddress((void**)&p_bsum, g_bsum);
    cudaGetSymbolAddress((void**)&p_eps, g_eps);
    cudaGetSymbolAddress((void**)&p_epd, g_epd);

    static cudaStream_t s2 = nullptr;
    static cudaEvent_t ev_fork = nullptr, ev_csr = nullptr, ev_join = nullptr;
    if (s2 == nullptr) {
        cudaStreamCreateWithFlags(&s2, cudaStreamNonBlocking);
        cudaEventCreateWithFlags(&ev_fork, cudaEventDisableTiming);
        cudaEventCreateWithFlags(&ev_csr,  cudaEventDisableTiming);
        cudaEventCreateWithFlags(&ev_join, cudaEventDisableTiming);
    }

    const int EB = (EE + 255) / 256;        // edge-parallel blocks
    const int NB = (NN + 7) / 8;            // warp-per-node blocks
    const int MB = (NN + 127) / 128;        // gemm row tiles
    const int SG = (NN + 1024) / 1024;      // scan blocks (covers NN+1)

    cudaMemsetAsync(p_cnt_s, 0, NN * sizeof(int));
    cudaMemsetAsync(p_cnt_d, 0, NN * sizeof(int));
    cudaMemsetAsync(p_sum, 0, 3 * HH * sizeof(float));
    cudaMemsetAsync(p_sumsq, 0, 3 * HH * sizeof(float));

    // fork s2 (QKV)
    cudaEventRecord(ev_fork, 0);
    cudaStreamWaitEvent(s2, ev_fork, 0);

    // s2: fused QKV GEMM (one launch, blockIdx.y selects q/k/v)
    k_gemm_tc<<<dim3(MB, 3), 256, 0, s2>>>(
        h, nullptr, wq, wk, wv, bq, bk, bv, nullptr,
        p_q, p_k, p_v, nullptr,
        NN, HH, HH, 0.25f, 0, /*qkv*/1, /*combine*/0, nullptr, nullptr);

    // main: CSR build (both directions)
    k_hist<<<EB, 256>>>(src, dst, p_cnt_s, p_cnt_d);
    k_scan_block<<<SG, 1024>>>(p_cnt_s, p_rp_s, &p_bsum[0]);
    k_scan_block<<<SG, 1024>>>(p_cnt_d, p_rp_d, &p_bsum[64]);
    k_scan_tops<<<1, 32>>>(&p_bsum[0], SG);
    k_scan_tops<<<1, 32>>>(&p_bsum[64], SG);
    k_scan_add<<<SG, 1024>>>(p_rp_s, &p_bsum[0]);
    k_scan_add<<<SG, 1024>>>(p_rp_d, &p_bsum[64]);
    k_scatter<<<EB, 256>>>(src, dst, p_rp_s, p_rp_d, p_cnt_s, p_cnt_d, p_eps, p_epd);
    cudaEventRecord(ev_csr, 0);

    // s2: fused attention (after QKV + CSR)
    cudaStreamWaitEvent(s2, ev_csr, 0);
    k_attn_csr<<<NB, 256, 0, s2>>>(h, p_q, p_k, p_v, p_rp_s, p_eps,
                                   p_ao, &p_sum[1 * HH], &p_sumsq[1 * HH]);
    cudaEventRecord(ev_join, s2);

    // main: GINE aggregate (fused eattr passthrough) + GIN MLP
    k_agg_csr<<<NB, 256>>>(h, eattr, p_rp_d, p_epd, p_agg, out_ea);
    k_gemm_tc<<<dim3(MB, 1), 256>>>(
        p_agg, nullptr, gin_w1, nullptr, nullptr, gin_b1, nullptr, nullptr, nullptr,
        p_buf1, nullptr, nullptr, nullptr,
        NN, HH, HH, 1.f, 1, 0, 0, nullptr, nullptr);
    k_gemm_tc<<<dim3(MB, 1), 256>>>(
        p_buf1, nullptr, gin_w2, nullptr, nullptr, gin_b2, nullptr, nullptr, h,
        p_agg, nullptr, nullptr, nullptr,
        NN, HH, HH, 1.f, 0, 0, 0, &p_sum[0 * HH], &p_sumsq[0 * HH]);

    // join attention branch
    cudaStreamWaitEvent(0, ev_join, 0);

    // finalize BNs 0/1; FFN1 fuses the combine (and materializes hc)
    k_bnfin01<<<1, 256>>>(nl_g, nl_b, na_g, na_b);
    k_gemm_tc<<<dim3(MB, 2), 256>>>(
        p_agg, p_ao, ffn1_w, nullptr, nullptr, ffn1_b, nullptr, nullptr, nullptr,
        p_buf1, nullptr, nullptr, p_hc,
        NN, 256, HH, 1.f, 1, 0, /*combine*/1, nullptr, nullptr);
    k_gemm_tc<<<dim3(MB, 1), 256>>>(
        p_buf1, nullptr, ffn2_w, nullptr, nullptr, ffn2_b, nullptr, nullptr, p_hc,
        p_hc, nullptr, nullptr, nullptr,
        NN, HH, 256, 1.f, 0, 0, 0, &p_sum[2 * HH], &p_sumsq[2 * HH]);
    k_bnfin<<<1, 128>>>(2, no_g, no_b);
    k_apply<<<(NN * 32 + 255) / 256, 256>>>(p_hc, out_hc);
}

// round 14
// speedup vs baseline: 1.1127x; 1.0832x over previous
#include <cuda_runtime.h>
#include <cuda_fp16.h>
#include <math.h>

#define NN 50000
#define EE 500000
#define HH 128
#define NHH 8
// DH = 16, scale = 0.25 (folded into q GEMM)

#define MAXDEG_SMEM 64

// ---------------- scratch (device globals; no runtime alloc) ----------------
__device__ float g_buf1[(size_t)NN * 256];  // gin hidden (N,128) then FFN hidden (N,256)
__device__ float g_agg [(size_t)NN * HH];   // z = h+agg -> xl (in-place)
__device__ __half g_qh [(size_t)NN * HH];
__device__ __half g_kh [(size_t)NN * HH];
__device__ __half g_vh [(size_t)NN * HH];
__device__ float g_ao  [(size_t)NN * HH];   // xa
__device__ float g_hc  [(size_t)NN * HH];   // combine -> +FFN (in-place)
__device__ float g_sum  [3][HH];
__device__ float g_sumsq[3][HH];
__device__ float g_bnA  [3][HH];
__device__ float g_bnB  [3][HH];
// CSR scratch
__device__ int  g_cnt_s[NN];
__device__ int  g_cnt_d[NN];
__device__ int  g_fill_s[NN];
__device__ int  g_fill_d[NN];
__device__ int  g_rp_s[NN + 1];
__device__ int  g_rp_d[NN + 1];
__device__ int  g_bsum[2][64];
__device__ int2 g_eps[EE];   // (dst, eid) sorted by src
__device__ int2 g_epd[EE];   // (src, eid) sorted by dst

// ---------------- small helpers ----------------
__device__ __forceinline__ void redf(float* p, float v) {
    asm volatile("red.global.add.f32 [%0], %1;" :: "l"(p), "f"(v) : "memory");
}
__device__ __forceinline__ float4 ldh4(const __half* p) {
    uint2 u = *(const uint2*)p;
    float2 a = __half22float2(*(const __half2*)&u.x);
    float2 b = __half22float2(*(const __half2*)&u.y);
    return make_float4(a.x, a.y, b.x, b.y);
}

// ---------------- CSR build ----------------
__global__ void k_hist(const int* __restrict__ src, const int* __restrict__ dst,
                       int* __restrict__ cs, int* __restrict__ cd) {
    int e = blockIdx.x * 256 + threadIdx.x;
    if (e >= EE) return;
    atomicAdd(&cs[src[e]], 1);
    atomicAdd(&cd[dst[e]], 1);
}

__global__ __launch_bounds__(1024) void k_scan_block(const int* __restrict__ cnt,
                                                     int* __restrict__ excl,
                                                     int* __restrict__ bsum) {
    __shared__ int sm[1024];
    int i = blockIdx.x * 1024 + threadIdx.x;
    int v = (i < NN) ? cnt[i] : 0;
    sm[threadIdx.x] = v;
    __syncthreads();
#pragma unroll
    for (int off = 1; off < 1024; off <<= 1) {
        int t = (threadIdx.x >= off) ? sm[threadIdx.x - off] : 0;
        __syncthreads();
        sm[threadIdx.x] += t;
        __syncthreads();
    }
    if (i <= NN) excl[i] = sm[threadIdx.x] - v;
    if (threadIdx.x == 1023) bsum[blockIdx.x] = sm[1023];
}

__global__ void k_scan_tops(int* __restrict__ bsum, int G) {
    if (threadIdx.x == 0) {
        int acc = 0;
        for (int b = 0; b < G; b++) { int t = bsum[b]; bsum[b] = acc; acc += t; }
    }
}

__global__ __launch_bounds__(1024) void k_scan_add(int* __restrict__ excl,
                                                   const int* __restrict__ bsum) {
    int i = blockIdx.x * 1024 + threadIdx.x;
    if (i <= NN) excl[i] += bsum[blockIdx.x];
}

__global__ void k_scatter(const int* __restrict__ src, const int* __restrict__ dst,
                          const int* __restrict__ rps, const int* __restrict__ rpd,
                          int* __restrict__ fills, int* __restrict__ filld,
                          int2* __restrict__ eps, int2* __restrict__ epd) {
    int e = blockIdx.x * 256 + threadIdx.x;
    if (e >= EE) return;
    int s = src[e], d = dst[e];
    int ps = rps[s] + atomicAdd(&fills[s], 1);
    eps[ps] = make_int2(d, e);
    int pd = rpd[d] + atomicAdd(&filld[d], 1);
    epd[pd] = make_int2(s, e);
}

// ---------------- GINE aggregate over dst-CSR (warp per node, no atomics) -------
__global__ __launch_bounds__(256) void k_agg_csr(
    const float* __restrict__ h, const float* __restrict__ ea,
    const int* __restrict__ rpd, const int2* __restrict__ epd,
    float* __restrict__ z, float* __restrict__ ea_out)
{
    int node = blockIdx.x * 8 + (threadIdx.x >> 5);
    if (node >= NN) return;
    int lane = threadIdx.x & 31;
    int j0 = rpd[node], j1 = rpd[node + 1];
    float4 acc = *(const float4*)(h + (size_t)node * HH + lane * 4);
    for (int j = j0; j < j1; j++) {
        int2 pr = __ldg(&epd[j]);
        float4 hv = *(const float4*)(h + (size_t)pr.x * HH + lane * 4);
        float4 ev = __ldcs((const float4*)(ea + (size_t)pr.y * HH + lane * 4));
        __stcs((float4*)(ea_out + (size_t)pr.y * HH + lane * 4), ev);
        acc.x += fmaxf(hv.x + ev.x, 0.f);
        acc.y += fmaxf(hv.y + ev.y, 0.f);
        acc.z += fmaxf(hv.z + ev.z, 0.f);
        acc.w += fmaxf(hv.w + ev.w, 0.f);
    }
    *(float4*)(z + (size_t)node * HH + lane * 4) = acc;
}

// ---------------- fused sparse attention over src-CSR (warp per node) ------------
// q/k/v stored as fp16 (half the gather traffic); math in fp32.
__global__ __launch_bounds__(256) void k_attn_csr(
    const float* __restrict__ h, const __half* __restrict__ q,
    const __half* __restrict__ k, const __half* __restrict__ v,
    const int* __restrict__ rps, const int2* __restrict__ eps,
    float* __restrict__ xa, float* __restrict__ sum, float* __restrict__ sumsq)
{
    __shared__ float pbuf[8][MAXDEG_SMEM][NHH];
    __shared__ float ss[HH], sq[HH];
    if (threadIdx.x < HH) { ss[threadIdx.x] = 0.f; sq[threadIdx.x] = 0.f; }
    __syncthreads();
    int wid = threadIdx.x >> 5;
    int lane = threadIdx.x & 31;
    int node = blockIdx.x * 8 + wid;
    if (node < NN) {
        int j0 = rps[node], j1 = rps[node + 1];
        int deg = j1 - j0;
        int hd = lane >> 2, t = lane & 3;
        float4 qv = ldh4(q + (size_t)node * HH + lane * 4);
        float den = 0.f;
        for (int j = 0; j < deg; j++) {
            int2 pr = __ldg(&eps[j0 + j]);
            float4 kv = ldh4(k + (size_t)pr.x * HH + lane * 4);
            float part = qv.x * kv.x + qv.y * kv.y + qv.z * kv.z + qv.w * kv.w;
            part += __shfl_xor_sync(0xffffffffu, part, 1);
            part += __shfl_xor_sync(0xffffffffu, part, 2);
            float pe = expf(part);
            den += pe;
            if (j < MAXDEG_SMEM && t == 0) pbuf[wid][j][hd] = pe;
        }
        __syncwarp();
        float inv = (deg > 0) ? 1.f / den : 0.f;
        float4 acc = make_float4(0.f, 0.f, 0.f, 0.f);
        for (int j = 0; j < deg; j++) {
            int2 pr = __ldg(&eps[j0 + j]);
            float w;
            if (j < MAXDEG_SMEM) {
                w = pbuf[wid][j][hd] * inv;
            } else {
                float4 kv = ldh4(k + (size_t)pr.x * HH + lane * 4);
                float part = qv.x * kv.x + qv.y * kv.y + qv.z * kv.z + qv.w * kv.w;
                part += __shfl_xor_sync(0xffffffffu, part, 1);
                part += __shfl_xor_sync(0xffffffffu, part, 2);
                w = expf(part) * inv;
            }
            float4 vv = ldh4(v + (size_t)pr.x * HH + lane * 4);
            acc.x += w * vv.x; acc.y += w * vv.y;
            acc.z += w * vv.z; acc.w += w * vv.w;
        }
        float4 hv = *(const float4*)(h + (size_t)node * HH + lane * 4);
        float4 o = make_float4(hv.x + acc.x, hv.y + acc.y, hv.z + acc.z, hv.w + acc.w);
        *(float4*)(xa + (size_t)node * HH + lane * 4) = o;
        atomicAdd(&ss[lane * 4 + 0], o.x); atomicAdd(&sq[lane * 4 + 0], o.x * o.x);
        atomicAdd(&ss[lane * 4 + 1], o.y); atomicAdd(&sq[lane * 4 + 1], o.y * o.y);
        atomicAdd(&ss[lane * 4 + 2], o.z); atomicAdd(&sq[lane * 4 + 2], o.z * o.z);
        atomicAdd(&ss[lane * 4 + 3], o.w); atomicAdd(&sq[lane * 4 + 3], o.w * o.w);
    }
    __syncthreads();
    if (threadIdx.x < HH) {
        redf(&sum[threadIdx.x], ss[threadIdx.x]);
        redf(&sumsq[threadIdx.x], sq[threadIdx.x]);
    }
}

// ---------------- FP16 tensor-core GEMM (fp32 accumulate) ----------------
// C[M,Nc] = act( ((A) @ W^T + bias) * scale ) [+res], optional fused column stats.
// out_half: write C as __half (no res/stats path used with this flag).
__global__ __launch_bounds__(256) void k_gemm_tc(
    const float* __restrict__ A,
    const float* __restrict__ W, const float* __restrict__ bias,
    const float* __restrict__ res, float* __restrict__ C,
    int M, int Nc, int K, float scale, int do_relu, int out_half,
    float* __restrict__ stat_sum, float* __restrict__ stat_sq)
{
    __shared__ __half2 As[128][20];
    __shared__ __half2 Bs[128][20];
    const int m0 = blockIdx.x * 128;
    const int n0 = blockIdx.y * 128;
    const int tid = threadIdx.x;
    const int wid = tid >> 5;
    const int lane = tid & 31;
    const int g = lane >> 2;
    const int t = lane & 3;
    const int wm = wid >> 1;
    const int wn = wid & 1;

    float acc[2][8][4];
#pragma unroll
    for (int mt = 0; mt < 2; mt++)
#pragma unroll
        for (int nt = 0; nt < 8; nt++)
#pragma unroll
            for (int c = 0; c < 4; c++) acc[mt][nt][c] = 0.f;

    for (int k0 = 0; k0 < K; k0 += 32) {
#pragma unroll
        for (int i = 0; i < 4; i++) {
            int idx = tid + i * 256;
            int r = idx >> 3;
            int c4 = (idx & 7) * 4;
            int ch = c4 >> 1;
            int gm = m0 + r;
            float4 va = make_float4(0.f, 0.f, 0.f, 0.f);
            if (gm < M) va = *(const float4*)(A + (size_t)gm * K + k0 + c4);
            As[r][ch + 0] = __floats2half2_rn(va.x, va.y);
            As[r][ch + 1] = __floats2half2_rn(va.z, va.w);
            float4 vb = *(const float4*)(W + (size_t)(n0 + r) * K + k0 + c4);
            Bs[r][ch + 0] = __floats2half2_rn(vb.x, vb.y);
            Bs[r][ch + 1] = __floats2half2_rn(vb.z, vb.w);
        }
        __syncthreads();

#pragma unroll
        for (int ks = 0; ks < 2; ks++) {
            const int kb = ks * 8;
            unsigned a[2][4];
#pragma unroll
            for (int mt = 0; mt < 2; mt++) {
                int r = wm * 32 + mt * 16 + g;
                a[mt][0] = *(const unsigned*)&As[r][kb + t];
                a[mt][1] = *(const unsigned*)&As[r + 8][kb + t];
                a[mt][2] = *(const unsigned*)&As[r][kb + t + 4];
                a[mt][3] = *(const unsigned*)&As[r + 8][kb + t + 4];
            }
            unsigned b[8][2];
#pragma unroll
            for (int nt = 0; nt < 8; nt++) {
                int r = wn * 64 + nt * 8 + g;
                b[nt][0] = *(const unsigned*)&Bs[r][kb + t];
                b[nt][1] = *(const unsigned*)&Bs[r][kb + t + 4];
            }
#pragma unroll
            for (int mt = 0; mt < 2; mt++)
#pragma unroll
                for (int nt = 0; nt < 8; nt++) {
                    asm volatile(
                        "mma.sync.aligned.m16n8k16.row.col.f32.f16.f16.f32 "
                        "{%0,%1,%2,%3}, {%4,%5,%6,%7}, {%8,%9}, {%0,%1,%2,%3};"
                        : "+f"(acc[mt][nt][0]), "+f"(acc[mt][nt][1]),
                          "+f"(acc[mt][nt][2]), "+f"(acc[mt][nt][3])
                        : "r"(a[mt][0]), "r"(a[mt][1]), "r"(a[mt][2]), "r"(a[mt][3]),
                          "r"(b[nt][0]), "r"(b[nt][1]));
                }
        }
        __syncthreads();
    }

#pragma unroll
    for (int nt = 0; nt < 8; nt++) {
        int gn = n0 + wn * 64 + nt * 8 + 2 * t;
        float b0 = bias[gn], b1 = bias[gn + 1];
        float cs0 = 0.f, cs1 = 0.f, cq0 = 0.f, cq1 = 0.f;
#pragma unroll
        for (int mt = 0; mt < 2; mt++) {
            int row = m0 + wm * 32 + mt * 16 + g;
            if (row < M) {
                float v0 = (acc[mt][nt][0] + b0) * scale;
                float v1 = (acc[mt][nt][1] + b1) * scale;
                if (do_relu) { v0 = fmaxf(v0, 0.f); v1 = fmaxf(v1, 0.f); }
                if (res) {
                    float2 rv = *(const float2*)(res + (size_t)row * Nc + gn);
                    v0 += rv.x; v1 += rv.y;
                }
                if (out_half) {
                    *(__half2*)((__half*)C + (size_t)row * Nc + gn) = __floats2half2_rn(v0, v1);
                } else {
                    *(float2*)(C + (size_t)row * Nc + gn) = make_float2(v0, v1);
                }
                cs0 += v0; cq0 += v0 * v0; cs1 += v1; cq1 += v1 * v1;
            }
            int row2 = row + 8;
            if (row2 < M) {
                float v2 = (acc[mt][nt][2] + b0) * scale;
                float v3 = (acc[mt][nt][3] + b1) * scale;
                if (do_relu) { v2 = fmaxf(v2, 0.f); v3 = fmaxf(v3, 0.f); }
                if (res) {
                    float2 rv = *(const float2*)(res + (size_t)row2 * Nc + gn);
                    v2 += rv.x; v3 += rv.y;
                }
                if (out_half) {
                    *(__half2*)((__half*)C + (size_t)row2 * Nc + gn) = __floats2half2_rn(v2, v3);
                } else {
                    *(float2*)(C + (size_t)row2 * Nc + gn) = make_float2(v2, v3);
                }
                cs0 += v2; cq0 += v2 * v2; cs1 += v3; cq1 += v3 * v3;
            }
        }
        if (stat_sum) {
#pragma unroll
            for (int off = 4; off <= 16; off <<= 1) {
                cs0 += __shfl_xor_sync(0xffffffffu, cs0, off);
                cs1 += __shfl_xor_sync(0xffffffffu, cs1, off);
                cq0 += __shfl_xor_sync(0xffffffffu, cq0, off);
                cq1 += __shfl_xor_sync(0xffffffffu, cq1, off);
            }
            if (g == 0) {
                redf(&stat_sum[gn], cs0); redf(&stat_sum[gn + 1], cs1);
                redf(&stat_sq[gn],  cq0); redf(&stat_sq[gn + 1],  cq1);
            }
        }
    }
}

// ---------------- BN finalize + apply ----------------
__global__ void k_bnfin01(const float* __restrict__ g0, const float* __restrict__ b0,
                          const float* __restrict__ g1, const float* __restrict__ b1) {
    int w = threadIdx.x >> 7;
    int c = threadIdx.x & 127;
    const float* g = w ? g1 : g0;
    const float* b = w ? b1 : b0;
    float mean = g_sum[w][c] * (1.f / NN);
    float var  = g_sumsq[w][c] * (1.f / NN) - mean * mean;
    float a = g[c] * rsqrtf(var + 1e-5f);
    g_bnA[w][c] = a;
    g_bnB[w][c] = b[c] - mean * a;
}

__global__ void k_bnfin(int which, const float* __restrict__ g, const float* __restrict__ b) {
    int c = threadIdx.x;
    float mean = g_sum[which][c] * (1.f / NN);
    float var  = g_sumsq[which][c] * (1.f / NN) - mean * mean;
    float a = g[c] * rsqrtf(var + 1e-5f);
    g_bnA[which][c] = a;
    g_bnB[which][c] = b[c] - mean * a;
}

__global__ void k_combine(const float* __restrict__ xl, const float* __restrict__ xa,
                          float* __restrict__ hc) {
    size_t i = (size_t)blockIdx.x * blockDim.x + threadIdx.x;
    if (i >= (size_t)NN * 32) return;
    int c4 = (int)(i & 31);
    float4 xlv = ((const float4*)xl)[i];
    float4 xav = ((const float4*)xa)[i];
    float4 a0 = *(const float4*)&g_bnA[0][c4 * 4];
    float4 b0 = *(const float4*)&g_bnB[0][c4 * 4];
    float4 a1 = *(const float4*)&g_bnA[1][c4 * 4];
    float4 b1 = *(const float4*)&g_bnB[1][c4 * 4];
    float4 o;
    o.x = a0.x * xlv.x + b0.x + a1.x * xav.x + b1.x;
    o.y = a0.y * xlv.y + b0.y + a1.y * xav.y + b1.y;
    o.z = a0.z * xlv.z + b0.z + a1.z * xav.z + b1.z;
    o.w = a0.w * xlv.w + b0.w + a1.w * xav.w + b1.w;
    ((float4*)hc)[i] = o;
}

__global__ void k_apply(const float* __restrict__ hc, float* __restrict__ out) {
    size_t i = (size_t)blockIdx.x * blockDim.x + threadIdx.x;
    if (i >= (size_t)NN * 32) return;
    int c4 = (int)(i & 31);
    float4 xv = ((const float4*)hc)[i];
    float4 a2 = *(const float4*)&g_bnA[2][c4 * 4];
    float4 b2 = *(const float4*)&g_bnB[2][c4 * 4];
    float4 o;
    o.x = a2.x * xv.x + b2.x;
    o.y = a2.y * xv.y + b2.y;
    o.z = a2.z * xv.z + b2.z;
    o.w = a2.w * xv.w + b2.w;
    ((float4*)out)[i] = o;
}

// ---------------- launcher ----------------
extern "C" void kernel_launch(void* const* d_in, const int* in_sizes, int n_in,
                              void* d_out, int out_size) {
    const float* h      = (const float*)d_in[0];
    const float* eattr  = (const float*)d_in[1];
    const int*   src    = (const int*)d_in[2];
    const int*   dst    = (const int*)d_in[3];
    const float* gin_w1 = (const float*)d_in[4];
    const float* gin_b1 = (const float*)d_in[5];
    const float* gin_w2 = (const float*)d_in[6];
    const float* gin_b2 = (const float*)d_in[7];
    const float* wq = (const float*)d_in[8];
    const float* bq = (const float*)d_in[9];
    const float* wk = (const float*)d_in[10];
    const float* bk = (const float*)d_in[11];
    const float* wv = (const float*)d_in[12];
    const float* bv = (const float*)d_in[13];
    const float* nl_g = (const float*)d_in[14];
    const float* nl_b = (const float*)d_in[15];
    const float* na_g = (const float*)d_in[16];
    const float* na_b = (const float*)d_in[17];
    const float* no_g = (const float*)d_in[18];
    const float* no_b = (const float*)d_in[19];
    const float* ffn1_w = (const float*)d_in[20];
    const float* ffn1_b = (const float*)d_in[21];
    const float* ffn2_w = (const float*)d_in[22];
    const float* ffn2_b = (const float*)d_in[23];

    float* out_hc = (float*)d_out;
    float* out_ea = (float*)d_out + (size_t)NN * HH;

    float *p_buf1, *p_agg, *p_ao, *p_hc, *p_sum, *p_sumsq;
    __half *p_qh, *p_kh, *p_vh;
    int *p_cnt_s, *p_cnt_d, *p_fill_s, *p_fill_d, *p_rp_s, *p_rp_d, *p_bsum;
    int2 *p_eps, *p_epd;
    cudaGetSymbolAddress((void**)&p_buf1, g_buf1);
    cudaGetSymbolAddress((void**)&p_agg,  g_agg);
    cudaGetSymbolAddress((void**)&p_qh,   g_qh);
    cudaGetSymbolAddress((void**)&p_kh,   g_kh);
    cudaGetSymbolAddress((void**)&p_vh,   g_vh);
    cudaGetSymbolAddress((void**)&p_ao,   g_ao);
    cudaGetSymbolAddress((void**)&p_hc,   g_hc);
    cudaGetSymbolAddress((void**)&p_sum,  g_sum);
    cudaGetSymbolAddress((void**)&p_sumsq, g_sumsq);
    cudaGetSymbolAddress((void**)&p_cnt_s, g_cnt_s);
    cudaGetSymbolAddress((void**)&p_cnt_d, g_cnt_d);
    cudaGetSymbolAddress((void**)&p_fill_s, g_fill_s);
    cudaGetSymbolAddress((void**)&p_fill_d, g_fill_d);
    cudaGetSymbolAddress((void**)&p_rp_s, g_rp_s);
    cudaGetSymbolAddress((void**)&p_rp_d, g_rp_d);
    cudaGetSymbolAddress((void**)&p_bsum, g_bsum);
    cudaGetSymbolAddress((void**)&p_eps, g_eps);
    cudaGetSymbolAddress((void**)&p_epd, g_epd);

    static cudaStream_t s2 = nullptr;
    static cudaEvent_t ev_fork = nullptr, ev_csr = nullptr, ev_join = nullptr;
    if (s2 == nullptr) {
        cudaStreamCreateWithFlags(&s2, cudaStreamNonBlocking);
        cudaEventCreateWithFlags(&ev_fork, cudaEventDisableTiming);
        cudaEventCreateWithFlags(&ev_csr,  cudaEventDisableTiming);
        cudaEventCreateWithFlags(&ev_join, cudaEventDisableTiming);
    }

    const int EB = (EE + 255) / 256;        // edge-parallel blocks
    const int NB = (NN + 7) / 8;            // warp-per-node blocks
    const int MB = (NN + 127) / 128;        // gemm row tiles
    const int SG = (NN + 1024) / 1024;      // scan blocks (covers NN+1)

    cudaMemsetAsync(p_cnt_s, 0, NN * sizeof(int));
    cudaMemsetAsync(p_cnt_d, 0, NN * sizeof(int));
    cudaMemsetAsync(p_fill_s, 0, NN * sizeof(int));
    cudaMemsetAsync(p_fill_d, 0, NN * sizeof(int));
    cudaMemsetAsync(p_sum, 0, 3 * HH * sizeof(float));
    cudaMemsetAsync(p_sumsq, 0, 3 * HH * sizeof(float));

    // fork: QKV GEMMs need only h — start immediately on s2 while main builds CSR
    cudaEventRecord(ev_fork, 0);
    cudaStreamWaitEvent(s2, ev_fork, 0);
    k_gemm_tc<<<dim3(MB, 1), 256, 0, s2>>>(h, wq, bq, nullptr, (float*)p_qh,
                                           NN, HH, HH, 0.25f, 0, 1, nullptr, nullptr);
    k_gemm_tc<<<dim3(MB, 1), 256, 0, s2>>>(h, wk, bk, nullptr, (float*)p_kh,
                                           NN, HH, HH, 1.f, 0, 1, nullptr, nullptr);
    k_gemm_tc<<<dim3(MB, 1), 256, 0, s2>>>(h, wv, bv, nullptr, (float*)p_vh,
                                           NN, HH, HH, 1.f, 0, 1, nullptr, nullptr);

    // main: CSR build (both directions)
    k_hist<<<EB, 256>>>(src, dst, p_cnt_s, p_cnt_d);
    k_scan_block<<<SG, 1024>>>(p_cnt_s, p_rp_s, &p_bsum[0]);
    k_scan_block<<<SG, 1024>>>(p_cnt_d, p_rp_d, &p_bsum[64]);
    k_scan_tops<<<1, 32>>>(&p_bsum[0], SG);
    k_scan_tops<<<1, 32>>>(&p_bsum[64], SG);
    k_scan_add<<<SG, 1024>>>(p_rp_s, &p_bsum[0]);
    k_scan_add<<<SG, 1024>>>(p_rp_d, &p_bsum[64]);
    k_scatter<<<EB, 256>>>(src, dst, p_rp_s, p_rp_d, p_fill_s, p_fill_d, p_eps, p_epd);
    cudaEventRecord(ev_csr, 0);

    // s2: fused attention (after QKV + CSR)
    cudaStreamWaitEvent(s2, ev_csr, 0);
    k_attn_csr<<<NB, 256, 0, s2>>>(h, p_qh, p_kh, p_vh, p_rp_s, p_eps,
                                   p_ao, &p_sum[1 * HH], &p_sumsq[1 * HH]);
    cudaEventRecord(ev_join, s2);

    // main: GINE aggregate (fused eattr passthrough) + GIN MLP
    k_agg_csr<<<NB, 256>>>(h, eattr, p_rp_d, p_epd, p_agg, out_ea);
    k_gemm_tc<<<dim3(MB, 1), 256>>>(p_agg, gin_w1, gin_b1, nullptr, p_buf1,
                                    NN, HH, HH, 1.f, 1, 0, nullptr, nullptr);
    k_gemm_tc<<<dim3(MB, 1), 256>>>(p_buf1, gin_w2, gin_b2, h, p_agg,
                                    NN, HH, HH, 1.f, 0, 0, &p_sum[0 * HH], &p_sumsq[0 * HH]);

    // join attention branch
    cudaStreamWaitEvent(0, ev_join, 0);

    // finalize BNs 0/1, combine, FFN, BN2, output
    k_bnfin01<<<1, 256>>>(nl_g, nl_b, na_g, na_b);
    k_combine<<<(NN * 32 + 255) / 256, 256>>>(p_agg, p_ao, p_hc);
    k_gemm_tc<<<dim3(MB, 2), 256>>>(p_hc, ffn1_w, ffn1_b, nullptr, p_buf1,
                                    NN, 256, HH, 1.f, 1, 0, nullptr, nullptr);
    k_gemm_tc<<<dim3(MB, 1), 256>>>(p_buf1, ffn2_w, ffn2_b, p_hc, p_hc,
                                    NN, HH, 256, 1.f, 0, 0, &p_sum[2 * HH], &p_sumsq[2 * HH]);
    k_bnfin<<<1, 128>>>(2, no_g, no_b);
    k_apply<<<(NN * 32 + 255) / 256, 256>>>(p_hc, out_hc);
}